// round 9
// baseline (speedup 1.0000x reference)
#include <cuda_runtime.h>
#include <cuda_fp16.h>
#include <math.h>
#include <stdint.h>

// B=1024, H=512. conv1 2->64 3x3 s1p1 (32x32) FUSED with conv2 64->128 3x3 s2p1
// (->16x16) in one per-image CTA. conv3 128->256 16x16 valid, GRU 512.
#define LEAK 0.01f

// ---------------- device scratch ----------------
__device__ __half g_w2h[128 * 576];                // conv2 weights [oc][tap*64+ic]
__device__ __half g_h2n[1024ull * 256 * 128];      // conv2 out NHWC fp16
__device__ __half g_c3wp[256ull * 32768];          // conv3 weights [n][p*128+oc]
__device__ __half g_xh[1024 * 512];                // GRU input fp16
__device__ __half g_hh16[1024 * 512];              // last_hh fp16
__device__ __half g_wih16[1536 * 512];
__device__ __half g_whh16[1536 * 512];
__device__ float g_part[16ull * 1024 * 256];       // conv3 split-K partials
__device__ float g_gi[1024 * 1536];
__device__ float g_gh[1024 * 1536];

__device__ __forceinline__ float leaky(float v) { return v >= 0.f ? v : LEAK * v; }

// ---------------- weight prep ----------------
__global__ void __launch_bounds__(256) w2p_kernel(const float* __restrict__ w) {
    int t = blockIdx.x * 256 + threadIdx.x;
    if (t >= 128 * 576) return;
    int oc = t / 576, k = t - oc * 576;
    int tap = k >> 6, ic = k & 63;
    g_w2h[t] = __float2half(w[oc * 576 + ic * 9 + tap]);
}

__global__ void c3t_kernel(const float* __restrict__ w) {
    __shared__ float t[32][33];
    int n = blockIdx.z, oc0 = blockIdx.y * 32, p0 = blockIdx.x * 32;
    int tx = threadIdx.x, ty = threadIdx.y;
#pragma unroll
    for (int rr = 0; rr < 4; rr++)
        t[ty + rr * 8][tx] = w[(size_t)n * 32768 + (size_t)(oc0 + ty + rr * 8) * 256 + p0 + tx];
    __syncthreads();
#pragma unroll
    for (int rr = 0; rr < 4; rr++)
        g_c3wp[(size_t)n * 32768 + (size_t)(p0 + ty + rr * 8) * 128 + oc0 + tx] =
            __float2half(t[tx][ty + rr * 8]);
}

__global__ void __launch_bounds__(256) cvt16_kernel(const float* __restrict__ src,
                                                    __half* __restrict__ dst, int n2) {
    int i = blockIdx.x * 256 + threadIdx.x;
    if (i >= n2) return;
    float2 v = ((const float2*)src)[i];
    ((__half2*)dst)[i] = __floats2half2_rn(v.x, v.y);
}

// ================= FUSED conv1 + conv2 (one CTA per image) ====================
// smem: in_s f32[2048] | w1s f32[1280] | b1s f32[64] | h1t 36992 words
//       (34x34x64 fp16, bank-swizzled) | Bs 2x4096 words (tap weight dbuf)
// Phase 1: conv1 in f32 FFMA -> fp16 smem tile (borders zeroed).
// Phase 2: conv2 implicit GEMM, CTA tile 256x128, warp 64x64, 9 taps x K=64.
// Swizzle: word block j of pos (y,x) stored at j ^ ((x>>1)&7) (x = padded coord).
#define H1T_WORDS 36992
#define FUSED_SMEM ((2048 + 1280 + 64) * 4 + H1T_WORDS * 4 + 2 * 4096 * 4)

__global__ void __launch_bounds__(256, 1) conv12_fused(const float* __restrict__ hm,
                                                       const float* __restrict__ w1,
                                                       const float* __restrict__ b1,
                                                       const float* __restrict__ b2) {
    extern __shared__ float sm[];
    float* in_s = sm;                     // 2048
    float* w1s = sm + 2048;               // 1280
    float* b1s = sm + 3328;               // 64
    uint32_t* h1t = (uint32_t*)(sm + 3392);
    uint32_t* Bs = h1t + H1T_WORDS;

    int tid = threadIdx.x;
    int b = blockIdx.x;
    int lane = tid & 31, wid = tid >> 5;
    int wm = wid & 3, wn = wid >> 2;       // 4m x 2n warps
    int gid = lane >> 2, tc = lane & 3;

    // ---- B(0) prefetch (overlaps phase 1) ----
    int boc = tid >> 1, bhalf = tid & 1;
    const __half* Bg = g_w2h + (size_t)boc * 576 + bhalf * 32;
    uint4 breg[4];
#pragma unroll
    for (int j = 0; j < 4; j++) breg[j] = ((const uint4*)Bg)[j];

    // ---- phase 1: conv1 ----
    const float4* src = (const float4*)(hm + (size_t)b * 2048);
    for (int i = tid; i < 512; i += 256) ((float4*)in_s)[i] = src[i];
    for (int i = tid; i < 1280; i += 256) {
        int oc = i / 20, k = i - oc * 20;
        w1s[i] = (k < 18) ? w1[oc * 18 + k] : 0.f;
    }
    if (tid < 64) b1s[tid] = b1[tid];
    // zero border positions of the padded tile
    for (int i = tid; i < 1156; i += 256) {
        int y = i / 34, x = i - y * 34;
        if (y == 0 || y == 33 || x == 0 || x == 33) {
            uint4 z = make_uint4(0, 0, 0, 0);
#pragma unroll
            for (int j = 0; j < 8; j++) ((uint4*)(h1t + i * 32))[j] = z;
        }
    }
    __syncthreads();

#pragma unroll
    for (int i = 0; i < 4; i++) {
        int p = tid + 256 * i;
        int y = p >> 5, x = p & 31;
        float v[18];
#pragma unroll
        for (int c = 0; c < 2; c++)
#pragma unroll
            for (int ky = 0; ky < 3; ky++)
#pragma unroll
                for (int kx = 0; kx < 3; kx++) {
                    int yy = y - 1 + ky, xx = x - 1 + kx;
                    float t = 0.f;
                    if (yy >= 0 && yy < 32 && xx >= 0 && xx < 32) t = in_s[c * 1024 + yy * 32 + xx];
                    v[c * 9 + ky * 3 + kx] = t;
                }
        int xp = x + 1, yp = y + 1;
        uint32_t base = (uint32_t)((yp * 34 + xp) * 32);
        uint32_t sx = (uint32_t)((xp >> 1) & 7);
#pragma unroll
        for (int o8 = 0; o8 < 8; o8++) {
            __half2 hp[4];
#pragma unroll
            for (int u = 0; u < 4; u++) {
                float pr[2];
#pragma unroll
                for (int g = 0; g < 2; g++) {
                    int oc = o8 * 8 + u * 2 + g;
                    const float4* wp = (const float4*)(w1s + oc * 20);
                    float4 w0 = wp[0], w1v = wp[1], w2 = wp[2], w3 = wp[3];
                    float2 w4 = *(const float2*)(w1s + oc * 20 + 16);
                    float acc = b1s[oc];
                    acc += v[0] * w0.x + v[1] * w0.y + v[2] * w0.z + v[3] * w0.w;
                    acc += v[4] * w1v.x + v[5] * w1v.y + v[6] * w1v.z + v[7] * w1v.w;
                    acc += v[8] * w2.x + v[9] * w2.y + v[10] * w2.z + v[11] * w2.w;
                    acc += v[12] * w3.x + v[13] * w3.y + v[14] * w3.z + v[15] * w3.w;
                    acc += v[16] * w4.x + v[17] * w4.y;
                    pr[g] = leaky(acc);
                }
                hp[u] = __floats2half2_rn(pr[0], pr[1]);
            }
            *(uint4*)(h1t + base + (((uint32_t)o8 ^ sx) << 2)) = *(uint4*)hp;
        }
    }

    // ---- phase 2: conv2 implicit GEMM ----
    float c[4][8][4];
#pragma unroll
    for (int mt = 0; mt < 4; mt++)
#pragma unroll
        for (int nt = 0; nt < 8; nt++)
#pragma unroll
            for (int q = 0; q < 4; q++) c[mt][nt][q] = 0.f;

    uint32_t bswz = (uint32_t)(boc & 7);
    for (int tap = 0; tap < 9; tap++) {
        uint32_t* Bb = Bs + (tap & 1) * 4096;
        // stage current tap weights (regs -> smem, swizzled)
#pragma unroll
        for (int j = 0; j < 4; j++) {
            uint32_t blk = (uint32_t)(bhalf * 4 + j) ^ bswz;
            *(uint4*)(Bb + boc * 32 + (blk << 2)) = breg[j];
        }
        __syncthreads();
        if (tap < 8) {
            const __half* Bn = Bg + (tap + 1) * 64;
#pragma unroll
            for (int j = 0; j < 4; j++) breg[j] = ((const uint4*)Bn)[j];
        }

        int ky = tap / 3, kx = tap - 3 * ky;
        int xo = 2 * gid + kx;
        uint32_t sxA = (uint32_t)((xo >> 1) & 7) << 2;
#pragma unroll
        for (int ks = 0; ks < 4; ks++) {
            uint32_t bq[8][2];
#pragma unroll
            for (int nt = 0; nt < 8; nt++) {
                int ocr = wn * 64 + nt * 8 + gid;
                uint32_t wB = (uint32_t)(ocr * 32) +
                              ((uint32_t)(ks * 8 + tc) ^ ((uint32_t)(ocr & 7) << 2));
                bq[nt][0] = Bb[wB];
                bq[nt][1] = Bb[wB ^ 4];
            }
#pragma unroll
            for (int mt = 0; mt < 4; mt++) {
                int y = 2 * (wm * 4 + mt) + ky;
                uint32_t wA = (uint32_t)((y * 34 + xo) * 32) +
                              ((uint32_t)(ks * 8 + tc) ^ sxA);
                uint32_t a0 = h1t[wA], a1 = h1t[wA + 512];
                uint32_t a2 = h1t[wA ^ 4], a3 = h1t[(wA + 512) ^ 4];
#pragma unroll
                for (int nt = 0; nt < 8; nt++) {
                    asm volatile(
                        "mma.sync.aligned.m16n8k16.row.col.f32.f16.f16.f32 "
                        "{%0,%1,%2,%3}, {%4,%5,%6,%7}, {%8,%9}, {%0,%1,%2,%3};"
                        : "+f"(c[mt][nt][0]), "+f"(c[mt][nt][1]),
                          "+f"(c[mt][nt][2]), "+f"(c[mt][nt][3])
                        : "r"(a0), "r"(a1), "r"(a2), "r"(a3),
                          "r"(bq[nt][0]), "r"(bq[nt][1]));
                }
            }
        }
        __syncthreads();
    }

    // ---- epilogue: bias + leaky -> g_h2n fp16 NHWC ----
    int m0 = b * 256;
#pragma unroll
    for (int mt = 0; mt < 4; mt++) {
        int r0 = m0 + wm * 64 + mt * 16 + gid;
#pragma unroll
        for (int nt = 0; nt < 8; nt++) {
            int col = wn * 64 + nt * 8 + 2 * tc;
            float bb0 = b2[col], bb1 = b2[col + 1];
            float v0 = leaky(c[mt][nt][0] + bb0), v1 = leaky(c[mt][nt][1] + bb1);
            float v2 = leaky(c[mt][nt][2] + bb0), v3 = leaky(c[mt][nt][3] + bb1);
            *(__half2*)(g_h2n + (size_t)r0 * 128 + col) = __floats2half2_rn(v0, v1);
            *(__half2*)(g_h2n + (size_t)(r0 + 8) * 128 + col) = __floats2half2_rn(v2, v3);
        }
    }
}

// ================= fp16 m16n8k16 generic GEMM (TN) =================
#define AS_H 9216   // 128*72 halves
#define BS_H 4608   // 64*72
#define SMEM_BYTES ((2 * (AS_H + BS_H)) * 2)

struct MmaCtx {
    int wm, wn, gid, tc;
    float c[2][4][4];
};

__device__ __forceinline__ void mma_chunk(const __half* As, const __half* Bs, MmaCtx& X) {
#pragma unroll
    for (int ks = 0; ks < 4; ks++) {
        uint32_t a[2][4], bq[4][2];
#pragma unroll
        for (int mt = 0; mt < 2; mt++) {
            const __half* ap = &As[(X.wm * 32 + mt * 16 + X.gid) * 72 + ks * 16 + X.tc * 2];
            a[mt][0] = *(const uint32_t*)ap;
            a[mt][1] = *(const uint32_t*)(ap + 8 * 72);
            a[mt][2] = *(const uint32_t*)(ap + 8);
            a[mt][3] = *(const uint32_t*)(ap + 8 * 72 + 8);
        }
#pragma unroll
        for (int nt = 0; nt < 4; nt++) {
            const __half* bp = &Bs[(X.wn * 32 + nt * 8 + X.gid) * 72 + ks * 16 + X.tc * 2];
            bq[nt][0] = *(const uint32_t*)bp;
            bq[nt][1] = *(const uint32_t*)(bp + 8);
        }
#pragma unroll
        for (int mt = 0; mt < 2; mt++)
#pragma unroll
            for (int nt = 0; nt < 4; nt++) {
                asm volatile(
                    "mma.sync.aligned.m16n8k16.row.col.f32.f16.f16.f32 "
                    "{%0,%1,%2,%3}, {%4,%5,%6,%7}, {%8,%9}, {%0,%1,%2,%3};"
                    : "+f"(X.c[mt][nt][0]), "+f"(X.c[mt][nt][1]),
                      "+f"(X.c[mt][nt][2]), "+f"(X.c[mt][nt][3])
                    : "r"(a[mt][0]), "r"(a[mt][1]), "r"(a[mt][2]), "r"(a[mt][3]),
                      "r"(bq[nt][0]), "r"(bq[nt][1]));
            }
    }
}

__global__ void __launch_bounds__(256) gemm_mma(const __half* __restrict__ A,
                                                const __half* __restrict__ B,
                                                float* __restrict__ C,
                                                const __half* __restrict__ A2,
                                                const __half* __restrict__ B2,
                                                float* __restrict__ C2,
                                                int ntile1,
                                                int lda, int ldb, int ldc, int kLen,
                                                long long cStride) {
    extern __shared__ __half smem[];
    __half* Asm = smem;
    __half* Bsm = smem + 2 * AS_H;

    int tid = threadIdx.x;
    MmaCtx X;
    int lane = tid & 31, wid = tid >> 5;
    X.wm = wid & 3; X.wn = wid >> 2;
    X.gid = lane >> 2; X.tc = lane & 3;
#pragma unroll
    for (int mt = 0; mt < 2; mt++)
#pragma unroll
        for (int nt = 0; nt < 4; nt++)
#pragma unroll
            for (int i = 0; i < 4; i++) X.c[mt][nt][i] = 0.f;

    int ny = blockIdx.y;
    if (ny >= ntile1) { A = A2; B = B2; C = C2; ny -= ntile1; }
    int m0 = blockIdx.x << 7, n0 = ny << 6;
    long long k0 = (long long)blockIdx.z * kLen;

    int arow = tid >> 1, ahalf = tid & 1;
    int brow = tid >> 2, bseg = tid & 3;
    const __half* Ap = A + (size_t)(m0 + arow) * lda + k0 + ahalf * 32;
    const __half* Bp = B + (size_t)(n0 + brow) * ldb + k0 + bseg * 16;

    int nc = kLen >> 6;
    uint4 ra[4], rb[2];
#pragma unroll
    for (int j = 0; j < 4; j++) ra[j] = ((const uint4*)Ap)[j];
#pragma unroll
    for (int j = 0; j < 2; j++) rb[j] = ((const uint4*)Bp)[j];

    uint32_t asts = arow * 72 + ahalf * 32;
    uint32_t bsts = brow * 72 + bseg * 16;
    {
#pragma unroll
        for (int j = 0; j < 4; j++) *(uint4*)&Asm[asts + 8 * j] = ra[j];
#pragma unroll
        for (int j = 0; j < 2; j++) *(uint4*)&Bsm[bsts + 8 * j] = rb[j];
    }
    __syncthreads();

    for (int ch = 0; ch < nc; ch++) {
        int nb = ch & 1;
        if (ch + 1 < nc) {
            Ap += 64; Bp += 64;
#pragma unroll
            for (int j = 0; j < 4; j++) ra[j] = ((const uint4*)Ap)[j];
#pragma unroll
            for (int j = 0; j < 2; j++) rb[j] = ((const uint4*)Bp)[j];
        }
        mma_chunk(Asm + nb * AS_H, Bsm + nb * BS_H, X);
        if (ch + 1 < nc) {
            __half* Ab = Asm + (nb ^ 1) * AS_H;
            __half* Bb = Bsm + (nb ^ 1) * BS_H;
#pragma unroll
            for (int j = 0; j < 4; j++) *(uint4*)&Ab[asts + 8 * j] = ra[j];
#pragma unroll
            for (int j = 0; j < 2; j++) *(uint4*)&Bb[bsts + 8 * j] = rb[j];
        }
        __syncthreads();
    }

    float* Cz = C + (long long)blockIdx.z * cStride;
#pragma unroll
    for (int mt = 0; mt < 2; mt++) {
        int r0 = m0 + X.wm * 32 + mt * 16 + X.gid;
#pragma unroll
        for (int nt = 0; nt < 4; nt++) {
            int col = n0 + X.wn * 32 + nt * 8 + 2 * X.tc;
            *(float2*)(Cz + (size_t)r0 * ldc + col) = make_float2(X.c[mt][nt][0], X.c[mt][nt][1]);
            *(float2*)(Cz + (size_t)(r0 + 8) * ldc + col) = make_float2(X.c[mt][nt][2], X.c[mt][nt][3]);
        }
    }
}

// ---------------- split-K reduce + conv3 bias/leaky + prebox -> g_xh ----------
__global__ void __launch_bounds__(256) build_x_kernel(const float* __restrict__ pre_box,
                                                      const float* __restrict__ pw,
                                                      const float* __restrict__ pb,
                                                      const float* __restrict__ c3b) {
    int t = blockIdx.x * 256 + threadIdx.x;
    int b = t >> 9, j = t & 511;
    float s;
    if (j < 256) {
        s = pb[j] + pre_box[b * 3] * pw[j * 3] + pre_box[b * 3 + 1] * pw[j * 3 + 1] +
            pre_box[b * 3 + 2] * pw[j * 3 + 2];
    } else {
        int n = j - 256;
        s = 0.f;
#pragma unroll
        for (int kz = 0; kz < 16; kz++) s += g_part[kz * 262144 + b * 256 + n];
        s += c3b[n];
        s = leaky(s);
    }
    g_xh[t] = __float2half(s);
}

// ---------------- GRU gates ----------------
__device__ __forceinline__ float sigmoid_t(float x) { return 0.5f + 0.5f * tanhf(0.5f * x); }

__global__ void __launch_bounds__(256) gates_kernel(const float* __restrict__ hh,
                                                    const float* __restrict__ bih,
                                                    const float* __restrict__ bhh,
                                                    float* __restrict__ out) {
    int t = blockIdx.x * 256 + threadIdx.x;
    int b = t >> 9, j = t & 511;
    size_t base = (size_t)b * 1536 + j;
    float ir = g_gi[base] + bih[j];
    float iz = g_gi[base + 512] + bih[512 + j];
    float inn = g_gi[base + 1024] + bih[1024 + j];
    float hr = g_gh[base] + bhh[j];
    float hz = g_gh[base + 512] + bhh[512 + j];
    float hn = g_gh[base + 1024] + bhh[1024 + j];
    float r = sigmoid_t(ir + hr);
    float z = sigmoid_t(iz + hz);
    float n = tanhf(inn + r * hn);
    float h0 = hh[t];
    float hnew = (1.f - z) * n + z * h0;
    out[t] = hnew;
    out[524288 + t] = hnew;
}

// ---------------- launch ----------------
extern "C" void kernel_launch(void* const* d_in, const int* in_sizes, int n_in,
                              void* d_out, int out_size) {
    (void)in_sizes; (void)n_in; (void)out_size;
    const float* pre_box = (const float*)d_in[0];
    const float* hm      = (const float*)d_in[1];
    const float* last_hh = (const float*)d_in[2];
    const float* pw      = (const float*)d_in[3];
    const float* pb      = (const float*)d_in[4];
    const float* c1w     = (const float*)d_in[5];
    const float* c1b     = (const float*)d_in[6];
    const float* c2w     = (const float*)d_in[7];
    const float* c2b     = (const float*)d_in[8];
    const float* c3w     = (const float*)d_in[9];
    const float* c3b     = (const float*)d_in[10];
    const float* wih     = (const float*)d_in[11];
    const float* whh     = (const float*)d_in[12];
    const float* bih     = (const float*)d_in[13];
    const float* bhh     = (const float*)d_in[14];
    float* out = (float*)d_out;

    __half *p_h2n, *p_c3wp, *p_xh, *p_hh16, *p_wih16, *p_whh16;
    float *p_part, *p_gi, *p_gh;
    cudaGetSymbolAddress((void**)&p_h2n, g_h2n);
    cudaGetSymbolAddress((void**)&p_c3wp, g_c3wp);
    cudaGetSymbolAddress((void**)&p_xh, g_xh);
    cudaGetSymbolAddress((void**)&p_hh16, g_hh16);
    cudaGetSymbolAddress((void**)&p_wih16, g_wih16);
    cudaGetSymbolAddress((void**)&p_whh16, g_whh16);
    cudaGetSymbolAddress((void**)&p_part, g_part);
    cudaGetSymbolAddress((void**)&p_gi, g_gi);
    cudaGetSymbolAddress((void**)&p_gh, g_gh);

    cudaFuncSetAttribute(conv12_fused, cudaFuncAttributeMaxDynamicSharedMemorySize, FUSED_SMEM);
    cudaFuncSetAttribute(gemm_mma, cudaFuncAttributeMaxDynamicSharedMemorySize, SMEM_BYTES);

    // launch order chosen so ncu (-s 5 -c 1) profiles conv12_fused (index 5)
    w2p_kernel<<<288, 256>>>(c2w);                                  // 0
    c3t_kernel<<<dim3(8, 4, 256), dim3(32, 8)>>>(c3w);              // 1
    cvt16_kernel<<<1536, 256>>>(wih, p_wih16, 393216);              // 2
    cvt16_kernel<<<1536, 256>>>(whh, p_whh16, 393216);              // 3
    cvt16_kernel<<<1024, 256>>>(last_hh, p_hh16, 262144);           // 4

    conv12_fused<<<1024, 256, FUSED_SMEM>>>(hm, c1w, c1b, c2b);     // 5

    // conv3: M=1024, N=256, K=32768, split-K 16
    gemm_mma<<<dim3(8, 4, 16), 256, SMEM_BYTES>>>(p_h2n, p_c3wp, p_part,
                                                  (const __half*)0, (const __half*)0, (float*)0,
                                                  1 << 30, 32768, 32768, 256, 2048, 262144LL);
    build_x_kernel<<<2048, 256>>>(pre_box, pw, pb, c3b);

    // fused GRU GEMMs: y<24 -> gi = x@wih^T, y>=24 -> gh = hh@whh^T
    gemm_mma<<<dim3(8, 48, 1), 256, SMEM_BYTES>>>(p_xh, p_wih16, p_gi,
                                                  p_hh16, p_whh16, p_gh,
                                                  24, 512, 512, 1536, 512, 0LL);

    gates_kernel<<<2048, 256>>>(last_hh, bih, bhh, out);
}

// round 11
// speedup vs baseline: 3.0208x; 3.0208x over previous
#include <cuda_runtime.h>
#include <cuda_fp16.h>
#include <math.h>
#include <stdint.h>

// B=1024, H=512. conv1 2->64 3x3 s1p1 (32x32), conv2 64->128 3x3 s2p1 (->16x16),
// conv3 128->256 16x16 valid (->1x1), GRU 512.  fp16 tensor-core path (f32 accum).
#define LEAK 0.01f

// ---------------- device scratch ----------------
// g_h1p: padded NHWC conv1 output [b][34][34][64] fp16; borders never written ->
// stay zero (the padding conv2 needs).
__device__ __half g_h1p[1024ull * 34 * 34 * 64];   // ~151MB
__device__ __half g_w2h[128 * 576];                // conv2 weights [oc][tap*64+ic]
__device__ __half g_h2n[1024ull * 256 * 128];      // conv2 out NHWC fp16
__device__ __half g_c3wp[256ull * 32768];          // conv3 weights [n][p*128+oc]
__device__ __half g_xh[1024 * 512];                // GRU input fp16
__device__ __half g_hh16[1024 * 512];              // last_hh fp16
__device__ __half g_wih16[1536 * 512];
__device__ __half g_whh16[1536 * 512];
__device__ float g_part[16ull * 1024 * 256];       // conv3 split-K partials
__device__ float g_gi[1024 * 1536];
__device__ float g_gh[1024 * 1536];

__device__ __forceinline__ float leaky(float v) { return v >= 0.f ? v : LEAK * v; }

// ---------------- conv1: 2->64 3x3 p1 + leaky -> padded NHWC fp16 -------------
__global__ void __launch_bounds__(256) conv1_kernel(const float* __restrict__ hm,
                                                    const float* __restrict__ w,
                                                    const float* __restrict__ bias) {
    __shared__ float in_s[2048];
    __shared__ float w_s[64 * 20];
    __shared__ float b_s[64];
    int b = blockIdx.x >> 2, q = blockIdx.x & 3;
    int tid = threadIdx.x;
    int yl = tid >> 5, x = tid & 31;
    int y = q * 8 + yl;

    const float4* src = (const float4*)(hm + (size_t)b * 2048);
    for (int i = tid; i < 512; i += 256) ((float4*)in_s)[i] = src[i];
    for (int i = tid; i < 1280; i += 256) {
        int oc = i / 20, k = i - oc * 20;
        w_s[i] = (k < 18) ? w[oc * 18 + k] : 0.f;
    }
    if (tid < 64) b_s[tid] = bias[tid];
    __syncthreads();

    float v[18];
#pragma unroll
    for (int c = 0; c < 2; c++)
#pragma unroll
        for (int ky = 0; ky < 3; ky++)
#pragma unroll
            for (int kx = 0; kx < 3; kx++) {
                int yy = y - 1 + ky, xx = x - 1 + kx;
                float t = 0.f;
                if (yy >= 0 && yy < 32 && xx >= 0 && xx < 32) t = in_s[c * 1024 + yy * 32 + xx];
                v[c * 9 + ky * 3 + kx] = t;
            }

    __half* dst = g_h1p + (((size_t)b * 34 + y + 1) * 34 + x + 1) * 64;
#pragma unroll 2
    for (int o8 = 0; o8 < 8; o8++) {
        __half2 hp[4];
#pragma unroll
        for (int u = 0; u < 4; u++) {
            float pr[2];
#pragma unroll
            for (int g = 0; g < 2; g++) {
                int oc = o8 * 8 + u * 2 + g;
                const float4* wp = (const float4*)(w_s + oc * 20);
                float4 w0 = wp[0], w1 = wp[1], w2 = wp[2], w3 = wp[3];
                float2 w4 = *(const float2*)(w_s + oc * 20 + 16);
                float acc = b_s[oc];
                acc += v[0] * w0.x + v[1] * w0.y + v[2] * w0.z + v[3] * w0.w;
                acc += v[4] * w1.x + v[5] * w1.y + v[6] * w1.z + v[7] * w1.w;
                acc += v[8] * w2.x + v[9] * w2.y + v[10] * w2.z + v[11] * w2.w;
                acc += v[12] * w3.x + v[13] * w3.y + v[14] * w3.z + v[15] * w3.w;
                acc += v[16] * w4.x + v[17] * w4.y;
                pr[g] = leaky(acc);
            }
            hp[u] = __floats2half2_rn(pr[0], pr[1]);
        }
        ((uint4*)dst)[o8] = *(uint4*)hp;
    }
}

// ---------------- weight prep ----------------
__global__ void __launch_bounds__(256) w2p_kernel(const float* __restrict__ w) {
    int t = blockIdx.x * 256 + threadIdx.x;
    if (t >= 128 * 576) return;
    int oc = t / 576, k = t - oc * 576;
    int tap = k >> 6, ic = k & 63;
    g_w2h[t] = __float2half(w[oc * 576 + ic * 9 + tap]);
}

__global__ void c3t_kernel(const float* __restrict__ w) {
    __shared__ float t[32][33];
    int n = blockIdx.z, oc0 = blockIdx.y * 32, p0 = blockIdx.x * 32;
    int tx = threadIdx.x, ty = threadIdx.y;
#pragma unroll
    for (int rr = 0; rr < 4; rr++)
        t[ty + rr * 8][tx] = w[(size_t)n * 32768 + (size_t)(oc0 + ty + rr * 8) * 256 + p0 + tx];
    __syncthreads();
#pragma unroll
    for (int rr = 0; rr < 4; rr++)
        g_c3wp[(size_t)n * 32768 + (size_t)(p0 + ty + rr * 8) * 128 + oc0 + tx] =
            __float2half(t[tx][ty + rr * 8]);
}

__global__ void __launch_bounds__(256) cvt16_kernel(const float* __restrict__ src,
                                                    __half* __restrict__ dst, int n2) {
    int i = blockIdx.x * 256 + threadIdx.x;
    if (i >= n2) return;
    float2 v = ((const float2*)src)[i];
    ((__half2*)dst)[i] = __floats2half2_rn(v.x, v.y);
}

// ================= fp16 m16n8k16 MMA, rows stride 72 halves =================
#define AS_H 9216   // 128*72 halves
#define BS_H 4608   // 64*72
#define SMEM_BYTES ((2 * (AS_H + BS_H)) * 2)
#define SMEM2_BYTES (4 * AS_H * 2)   // conv2: A dbuf + B dbuf, both 128x72

// ---------------- conv2 implicit GEMM: CTA tile 128x128, grid 2048 ------------
// x = image*2 + m-half. A rows = 128 output positions, B rows = all 128 oc.
__global__ void __launch_bounds__(256) conv2_mma(const float* __restrict__ bias) {
    extern __shared__ __half smem[];
    __half* Asm = smem;              // 2 x AS_H
    __half* Bsm = smem + 2 * AS_H;   // 2 x AS_H (128 rows x 72)

    int tid = threadIdx.x;
    int lane = tid & 31, wid = tid >> 5;
    int wm = wid & 3, wn = wid >> 2;          // 4m x 2n, warp tile 32x64
    int gid = lane >> 2, tc = lane & 3;

    float c[2][8][4];
#pragma unroll
    for (int mt = 0; mt < 2; mt++)
#pragma unroll
        for (int nt = 0; nt < 8; nt++)
#pragma unroll
            for (int q = 0; q < 4; q++) c[mt][nt][q] = 0.f;

    int bimg = blockIdx.x >> 1, halfb = blockIdx.x & 1;

    // A and B: 128 rows x 64 halves per chunk; thread loads 32 halves (4 uint4)
    int arow = tid >> 1, ahalf = tid & 1;
    int pos = halfb * 128 + arow;
    int oy = pos >> 4, ox = pos & 15;
    const __half* Abase = g_h1p + (((size_t)bimg * 34 + 2 * oy) * 34 + 2 * ox) * 64 + ahalf * 32;
    const __half* Bbase = g_w2h + (size_t)arow * 576 + ahalf * 32;

    const int tapoff[9] = {0, 64, 128, 34 * 64, 34 * 64 + 64, 34 * 64 + 128,
                           68 * 64, 68 * 64 + 64, 68 * 64 + 128};

    uint4 ra[4], rb[4];
#pragma unroll
    for (int j = 0; j < 4; j++) ra[j] = ((const uint4*)(Abase + tapoff[0]))[j];
#pragma unroll
    for (int j = 0; j < 4; j++) rb[j] = ((const uint4*)Bbase)[j];

    uint32_t sts = arow * 72 + ahalf * 32;
    {
#pragma unroll
        for (int j = 0; j < 4; j++) *(uint4*)&Asm[sts + 8 * j] = ra[j];
#pragma unroll
        for (int j = 0; j < 4; j++) *(uint4*)&Bsm[sts + 8 * j] = rb[j];
    }
    __syncthreads();

    for (int ch = 0; ch < 9; ch++) {
        int nb = ch & 1;
        if (ch + 1 < 9) {
            const __half* Ap = Abase + tapoff[ch + 1];
            const __half* Bp = Bbase + (ch + 1) * 64;
#pragma unroll
            for (int j = 0; j < 4; j++) ra[j] = ((const uint4*)Ap)[j];
#pragma unroll
            for (int j = 0; j < 4; j++) rb[j] = ((const uint4*)Bp)[j];
        }
        const __half* As = Asm + nb * AS_H;
        const __half* Bs = Bsm + nb * AS_H;
#pragma unroll
        for (int ks = 0; ks < 4; ks++) {
            uint32_t a[2][4], bq[8][2];
#pragma unroll
            for (int mt = 0; mt < 2; mt++) {
                const __half* ap = &As[(wm * 32 + mt * 16 + gid) * 72 + ks * 16 + tc * 2];
                a[mt][0] = *(const uint32_t*)ap;
                a[mt][1] = *(const uint32_t*)(ap + 8 * 72);
                a[mt][2] = *(const uint32_t*)(ap + 8);
                a[mt][3] = *(const uint32_t*)(ap + 8 * 72 + 8);
            }
#pragma unroll
            for (int nt = 0; nt < 8; nt++) {
                const __half* bp = &Bs[(wn * 64 + nt * 8 + gid) * 72 + ks * 16 + tc * 2];
                bq[nt][0] = *(const uint32_t*)bp;
                bq[nt][1] = *(const uint32_t*)(bp + 8);
            }
#pragma unroll
            for (int mt = 0; mt < 2; mt++)
#pragma unroll
                for (int nt = 0; nt < 8; nt++) {
                    asm volatile(
                        "mma.sync.aligned.m16n8k16.row.col.f32.f16.f16.f32 "
                        "{%0,%1,%2,%3}, {%4,%5,%6,%7}, {%8,%9}, {%0,%1,%2,%3};"
                        : "+f"(c[mt][nt][0]), "+f"(c[mt][nt][1]),
                          "+f"(c[mt][nt][2]), "+f"(c[mt][nt][3])
                        : "r"(a[mt][0]), "r"(a[mt][1]), "r"(a[mt][2]), "r"(a[mt][3]),
                          "r"(bq[nt][0]), "r"(bq[nt][1]));
                }
        }
        __syncthreads();
        if (ch + 1 < 9) {
            __half* Ab = Asm + (nb ^ 1) * AS_H;
            __half* Bb = Bsm + (nb ^ 1) * AS_H;
#pragma unroll
            for (int j = 0; j < 4; j++) *(uint4*)&Ab[sts + 8 * j] = ra[j];
#pragma unroll
            for (int j = 0; j < 4; j++) *(uint4*)&Bb[sts + 8 * j] = rb[j];
            __syncthreads();
        }
    }

    // epilogue: bias + leaky, write fp16 NHWC
    int m0 = bimg * 256 + halfb * 128;
#pragma unroll
    for (int mt = 0; mt < 2; mt++) {
        int r0 = m0 + wm * 32 + mt * 16 + gid;
#pragma unroll
        for (int nt = 0; nt < 8; nt++) {
            int col = wn * 64 + nt * 8 + 2 * tc;
            float b0 = bias[col], b1 = bias[col + 1];
            float v0 = leaky(c[mt][nt][0] + b0), v1 = leaky(c[mt][nt][1] + b1);
            float v2 = leaky(c[mt][nt][2] + b0), v3 = leaky(c[mt][nt][3] + b1);
            *(__half2*)(g_h2n + (size_t)r0 * 128 + col) = __floats2half2_rn(v0, v1);
            *(__half2*)(g_h2n + (size_t)(r0 + 8) * 128 + col) = __floats2half2_rn(v2, v3);
        }
    }
}

// ---------------- generic fp16 GEMM (TN): 128x64 tile, as in R7 ---------------
struct MmaCtx {
    int wm, wn, gid, tc;
    float c[2][4][4];
};

__device__ __forceinline__ void mma_chunk(const __half* As, const __half* Bs, MmaCtx& X) {
#pragma unroll
    for (int ks = 0; ks < 4; ks++) {
        uint32_t a[2][4], bq[4][2];
#pragma unroll
        for (int mt = 0; mt < 2; mt++) {
            const __half* ap = &As[(X.wm * 32 + mt * 16 + X.gid) * 72 + ks * 16 + X.tc * 2];
            a[mt][0] = *(const uint32_t*)ap;
            a[mt][1] = *(const uint32_t*)(ap + 8 * 72);
            a[mt][2] = *(const uint32_t*)(ap + 8);
            a[mt][3] = *(const uint32_t*)(ap + 8 * 72 + 8);
        }
#pragma unroll
        for (int nt = 0; nt < 4; nt++) {
            const __half* bp = &Bs[(X.wn * 32 + nt * 8 + X.gid) * 72 + ks * 16 + X.tc * 2];
            bq[nt][0] = *(const uint32_t*)bp;
            bq[nt][1] = *(const uint32_t*)(bp + 8);
        }
#pragma unroll
        for (int mt = 0; mt < 2; mt++)
#pragma unroll
            for (int nt = 0; nt < 4; nt++) {
                asm volatile(
                    "mma.sync.aligned.m16n8k16.row.col.f32.f16.f16.f32 "
                    "{%0,%1,%2,%3}, {%4,%5,%6,%7}, {%8,%9}, {%0,%1,%2,%3};"
                    : "+f"(X.c[mt][nt][0]), "+f"(X.c[mt][nt][1]),
                      "+f"(X.c[mt][nt][2]), "+f"(X.c[mt][nt][3])
                    : "r"(a[mt][0]), "r"(a[mt][1]), "r"(a[mt][2]), "r"(a[mt][3]),
                      "r"(bq[nt][0]), "r"(bq[nt][1]));
            }
    }
}

__global__ void __launch_bounds__(256) gemm_mma(const __half* __restrict__ A,
                                                const __half* __restrict__ B,
                                                float* __restrict__ C,
                                                const __half* __restrict__ A2,
                                                const __half* __restrict__ B2,
                                                float* __restrict__ C2,
                                                int ntile1,
                                                int lda, int ldb, int ldc, int kLen,
                                                long long cStride) {
    extern __shared__ __half smem[];
    __half* Asm = smem;
    __half* Bsm = smem + 2 * AS_H;

    int tid = threadIdx.x;
    MmaCtx X;
    int lane = tid & 31, wid = tid >> 5;
    X.wm = wid & 3; X.wn = wid >> 2;
    X.gid = lane >> 2; X.tc = lane & 3;
#pragma unroll
    for (int mt = 0; mt < 2; mt++)
#pragma unroll
        for (int nt = 0; nt < 4; nt++)
#pragma unroll
            for (int i = 0; i < 4; i++) X.c[mt][nt][i] = 0.f;

    int ny = blockIdx.y;
    if (ny >= ntile1) { A = A2; B = B2; C = C2; ny -= ntile1; }
    int m0 = blockIdx.x << 7, n0 = ny << 6;
    long long k0 = (long long)blockIdx.z * kLen;

    int arow = tid >> 1, ahalf = tid & 1;
    int brow = tid >> 2, bseg = tid & 3;
    const __half* Ap = A + (size_t)(m0 + arow) * lda + k0 + ahalf * 32;
    const __half* Bp = B + (size_t)(n0 + brow) * ldb + k0 + bseg * 16;

    int nc = kLen >> 6;
    uint4 ra[4], rb[2];
#pragma unroll
    for (int j = 0; j < 4; j++) ra[j] = ((const uint4*)Ap)[j];
#pragma unroll
    for (int j = 0; j < 2; j++) rb[j] = ((const uint4*)Bp)[j];

    uint32_t asts = arow * 72 + ahalf * 32;
    uint32_t bsts = brow * 72 + bseg * 16;
    {
#pragma unroll
        for (int j = 0; j < 4; j++) *(uint4*)&Asm[asts + 8 * j] = ra[j];
#pragma unroll
        for (int j = 0; j < 2; j++) *(uint4*)&Bsm[bsts + 8 * j] = rb[j];
    }
    __syncthreads();

    for (int ch = 0; ch < nc; ch++) {
        int nb = ch & 1;
        if (ch + 1 < nc) {
            Ap += 64; Bp += 64;
#pragma unroll
            for (int j = 0; j < 4; j++) ra[j] = ((const uint4*)Ap)[j];
#pragma unroll
            for (int j = 0; j < 2; j++) rb[j] = ((const uint4*)Bp)[j];
        }
        mma_chunk(Asm + nb * AS_H, Bsm + nb * BS_H, X);
        if (ch + 1 < nc) {
            __half* Ab = Asm + (nb ^ 1) * AS_H;
            __half* Bb = Bsm + (nb ^ 1) * BS_H;
#pragma unroll
            for (int j = 0; j < 4; j++) *(uint4*)&Ab[asts + 8 * j] = ra[j];
#pragma unroll
            for (int j = 0; j < 2; j++) *(uint4*)&Bb[bsts + 8 * j] = rb[j];
        }
        __syncthreads();
    }

    float* Cz = C + (long long)blockIdx.z * cStride;
#pragma unroll
    for (int mt = 0; mt < 2; mt++) {
        int r0 = m0 + X.wm * 32 + mt * 16 + X.gid;
#pragma unroll
        for (int nt = 0; nt < 4; nt++) {
            int col = n0 + X.wn * 32 + nt * 8 + 2 * X.tc;
            *(float2*)(Cz + (size_t)r0 * ldc + col) = make_float2(X.c[mt][nt][0], X.c[mt][nt][1]);
            *(float2*)(Cz + (size_t)(r0 + 8) * ldc + col) = make_float2(X.c[mt][nt][2], X.c[mt][nt][3]);
        }
    }
}

// ---------------- split-K reduce + conv3 bias/leaky + prebox -> g_xh ----------
__global__ void __launch_bounds__(256) build_x_kernel(const float* __restrict__ pre_box,
                                                      const float* __restrict__ pw,
                                                      const float* __restrict__ pb,
                                                      const float* __restrict__ c3b) {
    int t = blockIdx.x * 256 + threadIdx.x;
    int b = t >> 9, j = t & 511;
    float s;
    if (j < 256) {
        s = pb[j] + pre_box[b * 3] * pw[j * 3] + pre_box[b * 3 + 1] * pw[j * 3 + 1] +
            pre_box[b * 3 + 2] * pw[j * 3 + 2];
    } else {
        int n = j - 256;
        s = 0.f;
#pragma unroll
        for (int kz = 0; kz < 16; kz++) s += g_part[kz * 262144 + b * 256 + n];
        s += c3b[n];
        s = leaky(s);
    }
    g_xh[t] = __float2half(s);
}

// ---------------- GRU gates ----------------
__device__ __forceinline__ float sigmoid_t(float x) { return 0.5f + 0.5f * tanhf(0.5f * x); }

__global__ void __launch_bounds__(256) gates_kernel(const float* __restrict__ hh,
                                                    const float* __restrict__ bih,
                                                    const float* __restrict__ bhh,
                                                    float* __restrict__ out) {
    int t = blockIdx.x * 256 + threadIdx.x;
    int b = t >> 9, j = t & 511;
    size_t base = (size_t)b * 1536 + j;
    float ir = g_gi[base] + bih[j];
    float iz = g_gi[base + 512] + bih[512 + j];
    float inn = g_gi[base + 1024] + bih[1024 + j];
    float hr = g_gh[base] + bhh[j];
    float hz = g_gh[base + 512] + bhh[512 + j];
    float hn = g_gh[base + 1024] + bhh[1024 + j];
    float r = sigmoid_t(ir + hr);
    float z = sigmoid_t(iz + hz);
    float n = tanhf(inn + r * hn);
    float h0 = hh[t];
    float hnew = (1.f - z) * n + z * h0;
    out[t] = hnew;
    out[524288 + t] = hnew;
}

// ---------------- launch ----------------
extern "C" void kernel_launch(void* const* d_in, const int* in_sizes, int n_in,
                              void* d_out, int out_size) {
    (void)in_sizes; (void)n_in; (void)out_size;
    const float* pre_box = (const float*)d_in[0];
    const float* hm      = (const float*)d_in[1];
    const float* last_hh = (const float*)d_in[2];
    const float* pw      = (const float*)d_in[3];
    const float* pb      = (const float*)d_in[4];
    const float* c1w     = (const float*)d_in[5];
    const float* c1b     = (const float*)d_in[6];
    const float* c2w     = (const float*)d_in[7];
    const float* c2b     = (const float*)d_in[8];
    const float* c3w     = (const float*)d_in[9];
    const float* c3b     = (const float*)d_in[10];
    const float* wih     = (const float*)d_in[11];
    const float* whh     = (const float*)d_in[12];
    const float* bih     = (const float*)d_in[13];
    const float* bhh     = (const float*)d_in[14];
    float* out = (float*)d_out;

    __half *p_h2n, *p_c3wp, *p_xh, *p_hh16, *p_wih16, *p_whh16;
    float *p_part, *p_gi, *p_gh;
    cudaGetSymbolAddress((void**)&p_h2n, g_h2n);
    cudaGetSymbolAddress((void**)&p_c3wp, g_c3wp);
    cudaGetSymbolAddress((void**)&p_xh, g_xh);
    cudaGetSymbolAddress((void**)&p_hh16, g_hh16);
    cudaGetSymbolAddress((void**)&p_wih16, g_wih16);
    cudaGetSymbolAddress((void**)&p_whh16, g_whh16);
    cudaGetSymbolAddress((void**)&p_part, g_part);
    cudaGetSymbolAddress((void**)&p_gi, g_gi);
    cudaGetSymbolAddress((void**)&p_gh, g_gh);

    cudaFuncSetAttribute(conv2_mma, cudaFuncAttributeMaxDynamicSharedMemorySize, SMEM2_BYTES);
    cudaFuncSetAttribute(gemm_mma, cudaFuncAttributeMaxDynamicSharedMemorySize, SMEM_BYTES);

    // order: conv1/conv2 sit at indices 4/5 so ncu's sample window hits one
    w2p_kernel<<<288, 256>>>(c2w);                                  // 0
    cvt16_kernel<<<1536, 256>>>(wih, p_wih16, 393216);              // 1
    cvt16_kernel<<<1536, 256>>>(whh, p_whh16, 393216);              // 2
    cvt16_kernel<<<1024, 256>>>(last_hh, p_hh16, 262144);           // 3
    conv1_kernel<<<4096, 256>>>(hm, c1w, c1b);                      // 4
    conv2_mma<<<2048, 256, SMEM2_BYTES>>>(c2b);                     // 5
    c3t_kernel<<<dim3(8, 4, 256), dim3(32, 8)>>>(c3w);              // 6

    // conv3: M=1024, N=256, K=32768, split-K 16
    gemm_mma<<<dim3(8, 4, 16), 256, SMEM_BYTES>>>(p_h2n, p_c3wp, p_part,
                                                  (const __half*)0, (const __half*)0, (float*)0,
                                                  1 << 30, 32768, 32768, 256, 2048, 262144LL);
    build_x_kernel<<<2048, 256>>>(pre_box, pw, pb, c3b);

    // fused GRU GEMMs: y<24 -> gi = x@wih^T, y>=24 -> gh = hh@whh^T
    gemm_mma<<<dim3(8, 48, 1), 256, SMEM_BYTES>>>(p_xh, p_wih16, p_gi,
                                                  p_hh16, p_whh16, p_gh,
                                                  24, 512, 512, 1536, 512, 0LL);

    gates_kernel<<<2048, 256>>>(last_hh, bih, bhh, out);
}

// round 12
// speedup vs baseline: 3.1232x; 1.0339x over previous
#include <cuda_runtime.h>
#include <cuda_fp16.h>
#include <math.h>
#include <stdint.h>

// B=1024, H=512. conv1 2->64 3x3 s1p1 (32x32), conv2 64->128 3x3 s2p1 (->16x16),
// conv3 128->256 16x16 valid (->1x1), GRU 512.  fp16 tensor cores, ldmatrix frags.
#define LEAK 0.01f

// ---------------- device scratch ----------------
__device__ __half g_h1p[1024ull * 34 * 34 * 64];   // padded NHWC conv1 out (~151MB)
__device__ __half g_w2h[128 * 576];                // conv2 weights [oc][tap*64+ic]
__device__ __half g_h2n[1024ull * 256 * 128];      // conv2 out NHWC fp16
__device__ __half g_c3wp[256ull * 32768];          // conv3 weights [n][p*128+oc]
__device__ __half g_xh[1024 * 512];                // GRU input fp16
__device__ __half g_hh16[1024 * 512];              // last_hh fp16
__device__ __half g_wih16[1536 * 512];
__device__ __half g_whh16[1536 * 512];
__device__ float g_part[16ull * 1024 * 256];       // conv3 split-K partials
__device__ float g_gi[1024 * 1536];
__device__ float g_gh[1024 * 1536];

__device__ __forceinline__ float leaky(float v) { return v >= 0.f ? v : LEAK * v; }

__device__ __forceinline__ uint32_t s2u(const void* p) {
    return (uint32_t)__cvta_generic_to_shared(p);
}
__device__ __forceinline__ void ldm_x4(uint32_t& r0, uint32_t& r1, uint32_t& r2, uint32_t& r3,
                                       uint32_t addr) {
    asm volatile("ldmatrix.sync.aligned.m8n8.x4.shared.b16 {%0,%1,%2,%3}, [%4];"
                 : "=r"(r0), "=r"(r1), "=r"(r2), "=r"(r3) : "r"(addr));
}

// ---------------- conv1: 2->64 3x3 p1 + leaky -> padded NHWC fp16 -------------
__global__ void __launch_bounds__(256) conv1_kernel(const float* __restrict__ hm,
                                                    const float* __restrict__ w,
                                                    const float* __restrict__ bias) {
    __shared__ float in_s[2048];
    __shared__ float w_s[64 * 20];
    __shared__ float b_s[64];
    int b = blockIdx.x >> 2, q = blockIdx.x & 3;
    int tid = threadIdx.x;
    int yl = tid >> 5, x = tid & 31;
    int y = q * 8 + yl;

    const float4* src = (const float4*)(hm + (size_t)b * 2048);
    for (int i = tid; i < 512; i += 256) ((float4*)in_s)[i] = src[i];
    for (int i = tid; i < 1280; i += 256) {
        int oc = i / 20, k = i - oc * 20;
        w_s[i] = (k < 18) ? w[oc * 18 + k] : 0.f;
    }
    if (tid < 64) b_s[tid] = bias[tid];
    __syncthreads();

    float v[18];
#pragma unroll
    for (int c = 0; c < 2; c++)
#pragma unroll
        for (int ky = 0; ky < 3; ky++)
#pragma unroll
            for (int kx = 0; kx < 3; kx++) {
                int yy = y - 1 + ky, xx = x - 1 + kx;
                float t = 0.f;
                if (yy >= 0 && yy < 32 && xx >= 0 && xx < 32) t = in_s[c * 1024 + yy * 32 + xx];
                v[c * 9 + ky * 3 + kx] = t;
            }

    __half* dst = g_h1p + (((size_t)b * 34 + y + 1) * 34 + x + 1) * 64;
#pragma unroll 2
    for (int o8 = 0; o8 < 8; o8++) {
        __half2 hp[4];
#pragma unroll
        for (int u = 0; u < 4; u++) {
            float pr[2];
#pragma unroll
            for (int g = 0; g < 2; g++) {
                int oc = o8 * 8 + u * 2 + g;
                const float4* wp = (const float4*)(w_s + oc * 20);
                float4 w0 = wp[0], w1 = wp[1], w2 = wp[2], w3 = wp[3];
                float2 w4 = *(const float2*)(w_s + oc * 20 + 16);
                float acc = b_s[oc];
                acc += v[0] * w0.x + v[1] * w0.y + v[2] * w0.z + v[3] * w0.w;
                acc += v[4] * w1.x + v[5] * w1.y + v[6] * w1.z + v[7] * w1.w;
                acc += v[8] * w2.x + v[9] * w2.y + v[10] * w2.z + v[11] * w2.w;
                acc += v[12] * w3.x + v[13] * w3.y + v[14] * w3.z + v[15] * w3.w;
                acc += v[16] * w4.x + v[17] * w4.y;
                pr[g] = leaky(acc);
            }
            hp[u] = __floats2half2_rn(pr[0], pr[1]);
        }
        ((uint4*)dst)[o8] = *(uint4*)hp;
    }
}

// ---------------- weight prep ----------------
__global__ void __launch_bounds__(256) w2p_kernel(const float* __restrict__ w) {
    int t = blockIdx.x * 256 + threadIdx.x;
    if (t >= 128 * 576) return;
    int oc = t / 576, k = t - oc * 576;
    int tap = k >> 6, ic = k & 63;
    g_w2h[t] = __float2half(w[oc * 576 + ic * 9 + tap]);
}

__global__ void c3t_kernel(const float* __restrict__ w) {
    __shared__ float t[32][33];
    int n = blockIdx.z, oc0 = blockIdx.y * 32, p0 = blockIdx.x * 32;
    int tx = threadIdx.x, ty = threadIdx.y;
#pragma unroll
    for (int rr = 0; rr < 4; rr++)
        t[ty + rr * 8][tx] = w[(size_t)n * 32768 + (size_t)(oc0 + ty + rr * 8) * 256 + p0 + tx];
    __syncthreads();
#pragma unroll
    for (int rr = 0; rr < 4; rr++)
        g_c3wp[(size_t)n * 32768 + (size_t)(p0 + ty + rr * 8) * 128 + oc0 + tx] =
            __float2half(t[tx][ty + rr * 8]);
}

// one kernel converts wih | whh | last_hh (half2 units: 393216+393216+262144)
__global__ void __launch_bounds__(256) cvt_all_kernel(const float* __restrict__ wih,
                                                      const float* __restrict__ whh,
                                                      const float* __restrict__ hh) {
    int i = blockIdx.x * 256 + threadIdx.x;   // 0..1048575
    const float* src;
    __half* dst;
    int j;
    if (i < 393216) { src = wih; dst = g_wih16; j = i; }
    else if (i < 786432) { src = whh; dst = g_whh16; j = i - 393216; }
    else { src = hh; dst = g_hh16; j = i - 786432; }
    float2 v = ((const float2*)src)[j];
    ((__half2*)dst)[j] = __floats2half2_rn(v.x, v.y);
}

// ================= fp16 m16n8k16 MMA, rows stride 72 halves =================
#define AS_H 9216   // 128*72 halves
#define BS_H 4608   // 64*72
#define SMEM_BYTES ((2 * (AS_H + BS_H)) * 2)
#define SMEM2_BYTES (4 * AS_H * 2)   // conv2: A dbuf + B dbuf, both 128x72

// ---------------- conv2 implicit GEMM: CTA tile 128x128, grid 2048 ------------
__global__ void __launch_bounds__(256) conv2_mma(const float* __restrict__ bias) {
    extern __shared__ __half smem[];
    __half* Asm = smem;              // 2 x AS_H
    __half* Bsm = smem + 2 * AS_H;   // 2 x AS_H

    int tid = threadIdx.x;
    int lane = tid & 31, wid = tid >> 5;
    int wm = wid & 3, wn = wid >> 2;          // 4m x 2n, warp tile 32x64
    int gid = lane >> 2, tc = lane & 3;

    // ldmatrix per-lane offsets (halves)
    uint32_t aoff = (uint32_t)((wm * 32 + (lane & 7) + ((lane >> 3) & 1) * 8) * 72 +
                               ((lane >> 4) & 1) * 8);
    uint32_t boff = (uint32_t)((wn * 64 + (lane & 7) + ((lane >> 4) & 1) * 8) * 72 +
                               ((lane >> 3) & 1) * 8);

    float c[2][8][4];
#pragma unroll
    for (int mt = 0; mt < 2; mt++)
#pragma unroll
        for (int nt = 0; nt < 8; nt++)
#pragma unroll
            for (int q = 0; q < 4; q++) c[mt][nt][q] = 0.f;

    int bimg = blockIdx.x >> 1, halfb = blockIdx.x & 1;

    int arow = tid >> 1, ahalf = tid & 1;
    int pos = halfb * 128 + arow;
    int oy = pos >> 4, ox = pos & 15;
    const __half* Abase = g_h1p + (((size_t)bimg * 34 + 2 * oy) * 34 + 2 * ox) * 64 + ahalf * 32;
    const __half* Bbase = g_w2h + (size_t)arow * 576 + ahalf * 32;

    const int tapoff[9] = {0, 64, 128, 34 * 64, 34 * 64 + 64, 34 * 64 + 128,
                           68 * 64, 68 * 64 + 64, 68 * 64 + 128};

    uint4 ra[4], rb[4];
#pragma unroll
    for (int j = 0; j < 4; j++) ra[j] = ((const uint4*)(Abase + tapoff[0]))[j];
#pragma unroll
    for (int j = 0; j < 4; j++) rb[j] = ((const uint4*)Bbase)[j];

    uint32_t sts = arow * 72 + ahalf * 32;
    {
#pragma unroll
        for (int j = 0; j < 4; j++) *(uint4*)&Asm[sts + 8 * j] = ra[j];
#pragma unroll
        for (int j = 0; j < 4; j++) *(uint4*)&Bsm[sts + 8 * j] = rb[j];
    }
    __syncthreads();

    for (int ch = 0; ch < 9; ch++) {
        int nb = ch & 1;
        if (ch + 1 < 9) {
            const __half* Ap = Abase + tapoff[ch + 1];
            const __half* Bp = Bbase + (ch + 1) * 64;
#pragma unroll
            for (int j = 0; j < 4; j++) ra[j] = ((const uint4*)Ap)[j];
#pragma unroll
            for (int j = 0; j < 4; j++) rb[j] = ((const uint4*)Bp)[j];
        }
        uint32_t asb = s2u(Asm + nb * AS_H) + aoff * 2;
        uint32_t bsb = s2u(Bsm + nb * AS_H) + boff * 2;
#pragma unroll
        for (int ks = 0; ks < 4; ks++) {
            uint32_t a[2][4], bq[8][2];
#pragma unroll
            for (int mt = 0; mt < 2; mt++)
                ldm_x4(a[mt][0], a[mt][1], a[mt][2], a[mt][3],
                       asb + (uint32_t)(mt * 16 * 72 + ks * 16) * 2);
#pragma unroll
            for (int p = 0; p < 4; p++)
                ldm_x4(bq[2 * p][0], bq[2 * p][1], bq[2 * p + 1][0], bq[2 * p + 1][1],
                       bsb + (uint32_t)(p * 16 * 72 + ks * 16) * 2);
#pragma unroll
            for (int mt = 0; mt < 2; mt++)
#pragma unroll
                for (int nt = 0; nt < 8; nt++) {
                    asm volatile(
                        "mma.sync.aligned.m16n8k16.row.col.f32.f16.f16.f32 "
                        "{%0,%1,%2,%3}, {%4,%5,%6,%7}, {%8,%9}, {%0,%1,%2,%3};"
                        : "+f"(c[mt][nt][0]), "+f"(c[mt][nt][1]),
                          "+f"(c[mt][nt][2]), "+f"(c[mt][nt][3])
                        : "r"(a[mt][0]), "r"(a[mt][1]), "r"(a[mt][2]), "r"(a[mt][3]),
                          "r"(bq[nt][0]), "r"(bq[nt][1]));
                }
        }
        __syncthreads();
        if (ch + 1 < 9) {
            __half* Ab = Asm + (nb ^ 1) * AS_H;
            __half* Bb = Bsm + (nb ^ 1) * AS_H;
#pragma unroll
            for (int j = 0; j < 4; j++) *(uint4*)&Ab[sts + 8 * j] = ra[j];
#pragma unroll
            for (int j = 0; j < 4; j++) *(uint4*)&Bb[sts + 8 * j] = rb[j];
            __syncthreads();
        }
    }

    int m0 = bimg * 256 + halfb * 128;
#pragma unroll
    for (int mt = 0; mt < 2; mt++) {
        int r0 = m0 + wm * 32 + mt * 16 + gid;
#pragma unroll
        for (int nt = 0; nt < 8; nt++) {
            int col = wn * 64 + nt * 8 + 2 * tc;
            float b0 = bias[col], b1 = bias[col + 1];
            float v0 = leaky(c[mt][nt][0] + b0), v1 = leaky(c[mt][nt][1] + b1);
            float v2 = leaky(c[mt][nt][2] + b0), v3 = leaky(c[mt][nt][3] + b1);
            *(__half2*)(g_h2n + (size_t)r0 * 128 + col) = __floats2half2_rn(v0, v1);
            *(__half2*)(g_h2n + (size_t)(r0 + 8) * 128 + col) = __floats2half2_rn(v2, v3);
        }
    }
}

// ---------------- generic fp16 GEMM (TN): 128x64 tile, ldmatrix frags ---------
__global__ void __launch_bounds__(256) gemm_mma(const __half* __restrict__ A,
                                                const __half* __restrict__ B,
                                                float* __restrict__ C,
                                                const __half* __restrict__ A2,
                                                const __half* __restrict__ B2,
                                                float* __restrict__ C2,
                                                int ntile1,
                                                int lda, int ldb, int ldc, int kLen,
                                                long long cStride) {
    extern __shared__ __half smem[];
    __half* Asm = smem;
    __half* Bsm = smem + 2 * AS_H;

    int tid = threadIdx.x;
    int lane = tid & 31, wid = tid >> 5;
    int wm = wid & 3, wn = wid >> 2;
    int gid = lane >> 2, tc = lane & 3;

    uint32_t aoff = (uint32_t)((wm * 32 + (lane & 7) + ((lane >> 3) & 1) * 8) * 72 +
                               ((lane >> 4) & 1) * 8);
    uint32_t boff = (uint32_t)((wn * 32 + (lane & 7) + ((lane >> 4) & 1) * 8) * 72 +
                               ((lane >> 3) & 1) * 8);

    float c[2][4][4];
#pragma unroll
    for (int mt = 0; mt < 2; mt++)
#pragma unroll
        for (int nt = 0; nt < 4; nt++)
#pragma unroll
            for (int i = 0; i < 4; i++) c[mt][nt][i] = 0.f;

    int ny = blockIdx.y;
    if (ny >= ntile1) { A = A2; B = B2; C = C2; ny -= ntile1; }
    int m0 = blockIdx.x << 7, n0 = ny << 6;
    long long k0 = (long long)blockIdx.z * kLen;

    int arow = tid >> 1, ahalf = tid & 1;
    int brow = tid >> 2, bseg = tid & 3;
    const __half* Ap = A + (size_t)(m0 + arow) * lda + k0 + ahalf * 32;
    const __half* Bp = B + (size_t)(n0 + brow) * ldb + k0 + bseg * 16;

    int nc = kLen >> 6;
    uint4 ra[4], rb[2];
#pragma unroll
    for (int j = 0; j < 4; j++) ra[j] = ((const uint4*)Ap)[j];
#pragma unroll
    for (int j = 0; j < 2; j++) rb[j] = ((const uint4*)Bp)[j];

    uint32_t asts = arow * 72 + ahalf * 32;
    uint32_t bsts = brow * 72 + bseg * 16;
    {
#pragma unroll
        for (int j = 0; j < 4; j++) *(uint4*)&Asm[asts + 8 * j] = ra[j];
#pragma unroll
        for (int j = 0; j < 2; j++) *(uint4*)&Bsm[bsts + 8 * j] = rb[j];
    }
    __syncthreads();

    for (int ch = 0; ch < nc; ch++) {
        int nb = ch & 1;
        if (ch + 1 < nc) {
            Ap += 64; Bp += 64;
#pragma unroll
            for (int j = 0; j < 4; j++) ra[j] = ((const uint4*)Ap)[j];
#pragma unroll
            for (int j = 0; j < 2; j++) rb[j] = ((const uint4*)Bp)[j];
        }
        uint32_t asb = s2u(Asm + nb * AS_H) + aoff * 2;
        uint32_t bsb = s2u(Bsm + nb * BS_H) + boff * 2;
#pragma unroll
        for (int ks = 0; ks < 4; ks++) {
            uint32_t a[2][4], bq[4][2];
#pragma unroll
            for (int mt = 0; mt < 2; mt++)
                ldm_x4(a[mt][0], a[mt][1], a[mt][2], a[mt][3],
                       asb + (uint32_t)(mt * 16 * 72 + ks * 16) * 2);
#pragma unroll
            for (int p = 0; p < 2; p++)
                ldm_x4(bq[2 * p][0], bq[2 * p][1], bq[2 * p + 1][0], bq[2 * p + 1][1],
                       bsb + (uint32_t)(p * 16 * 72 + ks * 16) * 2);
#pragma unroll
            for (int mt = 0; mt < 2; mt++)
#pragma unroll
                for (int nt = 0; nt < 4; nt++) {
                    asm volatile(
                        "mma.sync.aligned.m16n8k16.row.col.f32.f16.f16.f32 "
                        "{%0,%1,%2,%3}, {%4,%5,%6,%7}, {%8,%9}, {%0,%1,%2,%3};"
                        : "+f"(c[mt][nt][0]), "+f"(c[mt][nt][1]),
                          "+f"(c[mt][nt][2]), "+f"(c[mt][nt][3])
                        : "r"(a[mt][0]), "r"(a[mt][1]), "r"(a[mt][2]), "r"(a[mt][3]),
                          "r"(bq[nt][0]), "r"(bq[nt][1]));
                }
        }
        __syncthreads();
        if (ch + 1 < nc) {
            __half* Ab = Asm + (nb ^ 1) * AS_H;
            __half* Bb = Bsm + (nb ^ 1) * BS_H;
#pragma unroll
            for (int j = 0; j < 4; j++) *(uint4*)&Ab[asts + 8 * j] = ra[j];
#pragma unroll
            for (int j = 0; j < 2; j++) *(uint4*)&Bb[bsts + 8 * j] = rb[j];
            __syncthreads();
        }
    }

    float* Cz = C + (long long)blockIdx.z * cStride;
#pragma unroll
    for (int mt = 0; mt < 2; mt++) {
        int r0 = m0 + wm * 32 + mt * 16 + gid;
#pragma unroll
        for (int nt = 0; nt < 4; nt++) {
            int col = n0 + wn * 32 + nt * 8 + 2 * tc;
            *(float2*)(Cz + (size_t)r0 * ldc + col) = make_float2(c[mt][nt][0], c[mt][nt][1]);
            *(float2*)(Cz + (size_t)(r0 + 8) * ldc + col) = make_float2(c[mt][nt][2], c[mt][nt][3]);
        }
    }
}

// ---------------- split-K reduce + conv3 bias/leaky + prebox -> g_xh ----------
__global__ void __launch_bounds__(256) build_x_kernel(const float* __restrict__ pre_box,
                                                      const float* __restrict__ pw,
                                                      const float* __restrict__ pb,
                                                      const float* __restrict__ c3b) {
    int t = blockIdx.x * 256 + threadIdx.x;
    int b = t >> 9, j = t & 511;
    float s;
    if (j < 256) {
        s = pb[j] + pre_box[b * 3] * pw[j * 3] + pre_box[b * 3 + 1] * pw[j * 3 + 1] +
            pre_box[b * 3 + 2] * pw[j * 3 + 2];
    } else {
        int n = j - 256;
        s = 0.f;
#pragma unroll
        for (int kz = 0; kz < 16; kz++) s += g_part[kz * 262144 + b * 256 + n];
        s += c3b[n];
        s = leaky(s);
    }
    g_xh[t] = __float2half(s);
}

// ---------------- GRU gates ----------------
__device__ __forceinline__ float sigmoid_t(float x) { return 0.5f + 0.5f * tanhf(0.5f * x); }

__global__ void __launch_bounds__(256) gates_kernel(const float* __restrict__ hh,
                                                    const float* __restrict__ bih,
                                                    const float* __restrict__ bhh,
                                                    float* __restrict__ out) {
    int t = blockIdx.x * 256 + threadIdx.x;
    int b = t >> 9, j = t & 511;
    size_t base = (size_t)b * 1536 + j;
    float ir = g_gi[base] + bih[j];
    float iz = g_gi[base + 512] + bih[512 + j];
    float inn = g_gi[base + 1024] + bih[1024 + j];
    float hr = g_gh[base] + bhh[j];
    float hz = g_gh[base + 512] + bhh[512 + j];
    float hn = g_gh[base + 1024] + bhh[1024 + j];
    float r = sigmoid_t(ir + hr);
    float z = sigmoid_t(iz + hz);
    float n = tanhf(inn + r * hn);
    float h0 = hh[t];
    float hnew = (1.f - z) * n + z * h0;
    out[t] = hnew;
    out[524288 + t] = hnew;
}

// ---------------- launch ----------------
extern "C" void kernel_launch(void* const* d_in, const int* in_sizes, int n_in,
                              void* d_out, int out_size) {
    (void)in_sizes; (void)n_in; (void)out_size;
    const float* pre_box = (const float*)d_in[0];
    const float* hm      = (const float*)d_in[1];
    const float* last_hh = (const float*)d_in[2];
    const float* pw      = (const float*)d_in[3];
    const float* pb      = (const float*)d_in[4];
    const float* c1w     = (const float*)d_in[5];
    const float* c1b     = (const float*)d_in[6];
    const float* c2w     = (const float*)d_in[7];
    const float* c2b     = (const float*)d_in[8];
    const float* c3w     = (const float*)d_in[9];
    const float* c3b     = (const float*)d_in[10];
    const float* wih     = (const float*)d_in[11];
    const float* whh     = (const float*)d_in[12];
    const float* bih     = (const float*)d_in[13];
    const float* bhh     = (const float*)d_in[14];
    float* out = (float*)d_out;

    __half *p_h2n, *p_c3wp, *p_xh, *p_hh16, *p_wih16, *p_whh16;
    float *p_part, *p_gi, *p_gh;
    cudaGetSymbolAddress((void**)&p_h2n, g_h2n);
    cudaGetSymbolAddress((void**)&p_c3wp, g_c3wp);
    cudaGetSymbolAddress((void**)&p_xh, g_xh);
    cudaGetSymbolAddress((void**)&p_hh16, g_hh16);
    cudaGetSymbolAddress((void**)&p_wih16, g_wih16);
    cudaGetSymbolAddress((void**)&p_whh16, g_whh16);
    cudaGetSymbolAddress((void**)&p_part, g_part);
    cudaGetSymbolAddress((void**)&p_gi, g_gi);
    cudaGetSymbolAddress((void**)&p_gh, g_gh);

    cudaFuncSetAttribute(conv2_mma, cudaFuncAttributeMaxDynamicSharedMemorySize, SMEM2_BYTES);
    cudaFuncSetAttribute(gemm_mma, cudaFuncAttributeMaxDynamicSharedMemorySize, SMEM_BYTES);

    w2p_kernel<<<288, 256>>>(c2w);                                  // 0
    cvt_all_kernel<<<4096, 256>>>(wih, whh, last_hh);               // 1
    conv1_kernel<<<4096, 256>>>(hm, c1w, c1b);                      // 2
    conv2_mma<<<2048, 256, SMEM2_BYTES>>>(c2b);                     // 3
    c3t_kernel<<<dim3(8, 4, 256), dim3(32, 8)>>>(c3w);              // 4

    // conv3: M=1024, N=256, K=32768, split-K 16
    gemm_mma<<<dim3(8, 4, 16), 256, SMEM_BYTES>>>(p_h2n, p_c3wp, p_part,
                                                  (const __half*)0, (const __half*)0, (float*)0,
                                                  1 << 30, 32768, 32768, 256, 2048, 262144LL);
    build_x_kernel<<<2048, 256>>>(pre_box, pw, pb, c3b);

    // fused GRU GEMMs: y<24 -> gi = x@wih^T, y>=24 -> gh = hh@whh^T
    gemm_mma<<<dim3(8, 48, 1), 256, SMEM_BYTES>>>(p_xh, p_wih16, p_gi,
                                                  p_hh16, p_whh16, p_gh,
                                                  24, 512, 512, 1536, 512, 0LL);

    gates_kernel<<<2048, 256>>>(last_hh, bih, bhh, out);
}